// round 10
// baseline (speedup 1.0000x reference)
#include <cuda_runtime.h>
#include <cuda_pipeline.h>
#include <mma.h>

using namespace nvcuda;

#define NTOK 65536          // B * H * W = 16 * 64 * 64
#define EDIM 512
#define EHID 2048
#define TD (NTOK * EDIM)    // elements per (token, dim) tensor

// ---------------- scratch (static device globals; no allocations) ----------------
__device__ float g_xw[TD];
__device__ float g_sw[TD];
__device__ float g_hw[TD];
__device__ float g_q[TD];
__device__ float g_k[TD];
__device__ float g_v[TD];
__device__ float g_vs[TD];
__device__ float g_vh[TD];
__device__ float g_o[TD];
__device__ float g_os[TD];
__device__ float g_oh[TD];
__device__ float g_hid[NTOK * EHID];

// windowed token t -> original token (also the window-reverse scatter target)
__device__ __forceinline__ int winrev_row(int t) {
    int b   = t >> 12;          // 4096 tokens per image
    int win = (t >> 6) & 63;    // wh*8 + ww
    int n   = t & 63;           // nh*8 + nw
    int oh  = (((win >> 3) << 3) + (n >> 3) + 4) & 63;
    int ow  = (((win & 7) << 3) + (n & 7) + 4) & 63;
    return (b << 12) + (oh << 6) + ow;
}

// ---------------- gather: cyclic shift (-4,-4) + window partition ----------------
__global__ __launch_bounds__(128) void gather3(
    const float* __restrict__ x, const float* __restrict__ s, const float* __restrict__ h,
    float* __restrict__ xw, float* __restrict__ sw, float* __restrict__ hw)
{
    int t = blockIdx.x;
    int c = threadIdx.x << 2;
    size_t src = (size_t)winrev_row(t) * EDIM + c;
    size_t dst = (size_t)t * EDIM + c;
    *(float4*)(xw + dst) = *(const float4*)(x + src);
    *(float4*)(sw + dst) = *(const float4*)(s + src);
    *(float4*)(hw + dst) = *(const float4*)(h + src);
}

// ---------------- tf32 wmma GEMM v3: 128x256 tile, 64x64 warp tile, cp.async ----------
// A: M x K row-major, B: K x N row-major. fp32 operands; HMMA truncates to tf32 (RZ).
// mode 0: C = alpha * val
// mode 1: C = relu(val)
// mode 2: C += val                (in-place residual accumulate)
// mode 3: C[map(row)] = res[map(row)] + val   (window-reverse scatter + residual)
#define BM 128
#define BN 256
#define BK 16
#define A_PAD 20            // 128x16 tile stored at stride 20 (bank-conflict-free)
#define B_PAD 260           // 16x256 tile stored at stride 260
#define A_STAGE (BM * A_PAD)        // 2560 floats
#define B_STAGE (BK * B_PAD)        // 4160 floats
#define GEMM_SMEM ((2 * A_STAGE + 2 * B_STAGE) * 4)   // 53,760 bytes

__global__ __launch_bounds__(256) void gemm_tf32_v3(
    const float* __restrict__ A, const float* __restrict__ Bm,
    const float* __restrict__ bias, float* __restrict__ C,
    const float* __restrict__ res,
    int M, int N, int K, int mode, float alpha)
{
    extern __shared__ float sm[];
    float* As = sm;                          // 2 stages of 128x20
    float* Bs = sm + 2 * A_STAGE;            // 2 stages of 16x260

    int tid = threadIdx.x;
    int warp = tid >> 5;
    int wm = warp >> 2;                      // 0..1: 64-row band
    int wn = warp & 3;                       // 0..3: 64-col band
    int m0 = blockIdx.y * BM;
    int n0 = blockIdx.x * BN;

    wmma::fragment<wmma::accumulator, 16, 16, 8, float> acc[4][4];
    #pragma unroll
    for (int i = 0; i < 4; i++)
        #pragma unroll
        for (int j = 0; j < 4; j++) wmma::fill_fragment(acc[i][j], 0.0f);

    // async tile loader: A 512 float4 (2/thread), B 1024 float4 (4/thread)
    auto load_tile = [&](int s, int ko) {
        float* as = As + s * A_STAGE;
        float* bs = Bs + s * B_STAGE;
        #pragma unroll
        for (int i = 0; i < 2; i++) {
            int id = tid * 2 + i;
            int r = id >> 2, c = (id & 3) << 2;
            __pipeline_memcpy_async(as + r * A_PAD + c,
                                    A + (size_t)(m0 + r) * K + ko + c, 16);
        }
        #pragma unroll
        for (int i = 0; i < 4; i++) {
            int id = tid * 4 + i;
            int r = id >> 6, c = (id & 63) << 2;
            __pipeline_memcpy_async(bs + r * B_PAD + c,
                                    Bm + (size_t)(ko + r) * N + n0 + c, 16);
        }
    };

    int ktiles = K / BK;
    load_tile(0, 0);
    __pipeline_commit();

    for (int kt = 0; kt < ktiles; kt++) {
        if (kt + 1 < ktiles) {
            load_tile((kt + 1) & 1, (kt + 1) * BK);
            __pipeline_commit();
        }
        __pipeline_wait_prior(kt + 1 < ktiles ? 1 : 0);
        __syncthreads();

        float* as = As + (kt & 1) * A_STAGE;
        float* bs = Bs + (kt & 1) * B_STAGE;
        #pragma unroll
        for (int ks = 0; ks < BK; ks += 8) {
            wmma::fragment<wmma::matrix_a, 16, 16, 8, wmma::precision::tf32, wmma::row_major> af[4];
            wmma::fragment<wmma::matrix_b, 16, 16, 8, wmma::precision::tf32, wmma::row_major> bf[4];
            #pragma unroll
            for (int i = 0; i < 4; i++)
                wmma::load_matrix_sync(af[i], as + (wm * 64 + i * 16) * A_PAD + ks, A_PAD);
            #pragma unroll
            for (int j = 0; j < 4; j++)
                wmma::load_matrix_sync(bf[j], bs + ks * B_PAD + wn * 64 + j * 16, B_PAD);
            #pragma unroll
            for (int i = 0; i < 4; i++)
                #pragma unroll
                for (int j = 0; j < 4; j++)
                    wmma::mma_sync(acc[i][j], af[i], bf[j], acc[i][j]);
        }
        __syncthreads();
    }

    // epilogue: four 32x256 quarters staged through smem (stride 260)
    #pragma unroll 1
    for (int q = 0; q < 4; q++) {
        if (wm == (q >> 1)) {
            int i0 = (q & 1) * 2;
            #pragma unroll
            for (int ii = 0; ii < 2; ii++)
                #pragma unroll
                for (int j = 0; j < 4; j++)
                    wmma::store_matrix_sync(sm + (ii * 16) * B_PAD + wn * 64 + j * 16,
                                            acc[i0 + ii][j], B_PAD, wmma::mem_row_major);
        }
        __syncthreads();
        // 32*256/4 = 2048 float4, 8 per thread
        for (int e = tid; e < 2048; e += 256) {
            int r = e >> 6;
            int c = (e & 63) << 2;
            float4 val = *(float4*)(sm + r * B_PAD + c);
            int gn = n0 + c;
            float4 bb = *(const float4*)(bias + gn);
            val.x += bb.x; val.y += bb.y; val.z += bb.z; val.w += bb.w;
            int gm = m0 + q * 32 + r;
            if (mode == 0) {
                val.x *= alpha; val.y *= alpha; val.z *= alpha; val.w *= alpha;
                *(float4*)(C + (size_t)gm * N + gn) = val;
            } else if (mode == 1) {
                val.x = fmaxf(val.x, 0.f); val.y = fmaxf(val.y, 0.f);
                val.z = fmaxf(val.z, 0.f); val.w = fmaxf(val.w, 0.f);
                *(float4*)(C + (size_t)gm * N + gn) = val;
            } else if (mode == 2) {
                float4 cv = *(float4*)(C + (size_t)gm * N + gn);
                val.x += cv.x; val.y += cv.y; val.z += cv.z; val.w += cv.w;
                *(float4*)(C + (size_t)gm * N + gn) = val;
            } else {
                size_t off = (size_t)winrev_row(gm) * N + gn;
                float4 rv = *(const float4*)(res + off);
                val.x += rv.x; val.y += rv.y; val.z += rv.z; val.w += rv.w;
                *(float4*)(C + off) = val;
            }
        }
        __syncthreads();
    }
}

// ---------------- attention: one block per (window, head) ----------------
// dynamic smem (49,664 B): qs 64x64 (reused for V), ktr stride-65, ps stride-65
#define PS_STRIDE 65
__global__ __launch_bounds__(256) void attn_kernel(
    const float* __restrict__ q, const float* __restrict__ k,
    const float* __restrict__ v, const float* __restrict__ vs, const float* __restrict__ vh,
    const float* __restrict__ rpb,
    float* __restrict__ o, float* __restrict__ os, float* __restrict__ oh)
{
    extern __shared__ float dsm[];
    float* qs  = dsm;                 // 64*64 = 4096
    float* ktr = dsm + 4096;          // 64*65 = 4160, kt[d*65 + m]
    float* ps  = dsm + 4096 + 4160;   // 64*65 = 4160, ps[n*65 + m]

    int win = blockIdx.x;
    int head = blockIdx.y;
    int tid = threadIdx.x;
    size_t base = (size_t)win * 64 * EDIM + head * 64;

    for (int f4 = tid; f4 < 1024; f4 += 256) {
        int n = f4 >> 4;
        int c = (f4 & 15) << 2;
        float4 qv = *(const float4*)(q + base + (size_t)n * EDIM + c);
        *(float4*)(qs + n * 64 + c) = qv;
        float4 kv = *(const float4*)(k + base + (size_t)n * EDIM + c);
        ktr[(c + 0) * 65 + n] = kv.x;
        ktr[(c + 1) * 65 + n] = kv.y;
        ktr[(c + 2) * 65 + n] = kv.z;
        ktr[(c + 3) * 65 + n] = kv.w;
    }
    __syncthreads();

    int n0 = (tid >> 4) << 2;
    int m0 = (tid & 15) << 2;

    float acc[4][4];
    #pragma unroll
    for (int i = 0; i < 4; i++)
        #pragma unroll
        for (int j = 0; j < 4; j++) acc[i][j] = 0.f;

    #pragma unroll 4
    for (int d = 0; d < 64; d++) {
        float qr[4], kr[4];
        #pragma unroll
        for (int i = 0; i < 4; i++) qr[i] = qs[(n0 + i) * 64 + d];
        #pragma unroll
        for (int j = 0; j < 4; j++) kr[j] = ktr[d * 65 + m0 + j];
        #pragma unroll
        for (int i = 0; i < 4; i++)
            #pragma unroll
            for (int j = 0; j < 4; j++)
                acc[i][j] = fmaf(qr[i], kr[j], acc[i][j]);
    }

    // rel-pos bias + shifted-window mask (window coordinates, unrolled mask grid)
    int wi = win & 63;
    int wh = wi >> 3, ww = wi & 7;
    #pragma unroll
    for (int i = 0; i < 4; i++) {
        int nn = n0 + i;
        int ni = nn >> 3, nj = nn & 7;
        int yn = wh * 8 + ni, xn = ww * 8 + nj;
        int idn = ((yn < 56) ? 0 : (yn < 60) ? 1 : 2) * 3 +
                  ((xn < 56) ? 0 : (xn < 60) ? 1 : 2);
        #pragma unroll
        for (int j = 0; j < 4; j++) {
            int mm = m0 + j;
            int mi = mm >> 3, mj = mm & 7;
            float rb = rpb[(((ni - mi + 7) * 15) + (nj - mj + 7)) * 8 + head];
            int ym = wh * 8 + mi, xm = ww * 8 + mj;
            int idm = ((ym < 56) ? 0 : (ym < 60) ? 1 : 2) * 3 +
                      ((xm < 56) ? 0 : (xm < 60) ? 1 : 2);
            float msk = (idn == idm) ? 0.f : -100.f;
            ps[nn * PS_STRIDE + mm] = acc[i][j] + rb + msk;
        }
    }
    __syncthreads();

    // softmax: one thread per row (stride-65 -> conflict-free)
    if (tid < 64) {
        float mx = -1e30f;
        for (int m = 0; m < 64; m++) mx = fmaxf(mx, ps[tid * PS_STRIDE + m]);
        float sum = 0.f;
        for (int m = 0; m < 64; m++) {
            float e = __expf(ps[tid * PS_STRIDE + m] - mx);
            ps[tid * PS_STRIDE + m] = e;
            sum += e;
        }
        float inv = 1.f / sum;
        for (int m = 0; m < 64; m++) ps[tid * PS_STRIDE + m] *= inv;
    }

    const float* vptr[3] = {v, vs, vh};
    float* optr[3] = {o, os, oh};
    #pragma unroll 1
    for (int t3 = 0; t3 < 3; t3++) {
        __syncthreads();                                  // qs free to reuse
        const float* vp = vptr[t3];
        for (int f4 = tid; f4 < 1024; f4 += 256) {
            int n = f4 >> 4;
            int c = (f4 & 15) << 2;
            *(float4*)(qs + n * 64 + c) = *(const float4*)(vp + base + (size_t)n * EDIM + c);
        }
        __syncthreads();
        float oa[4][4];
        #pragma unroll
        for (int i = 0; i < 4; i++)
            #pragma unroll
            for (int j = 0; j < 4; j++) oa[i][j] = 0.f;
        #pragma unroll 4
        for (int m = 0; m < 64; m++) {
            float pr[4];
            #pragma unroll
            for (int i = 0; i < 4; i++) pr[i] = ps[(n0 + i) * PS_STRIDE + m];
            float4 vv = *(const float4*)(qs + m * 64 + m0);
            #pragma unroll
            for (int i = 0; i < 4; i++) {
                oa[i][0] = fmaf(pr[i], vv.x, oa[i][0]);
                oa[i][1] = fmaf(pr[i], vv.y, oa[i][1]);
                oa[i][2] = fmaf(pr[i], vv.z, oa[i][2]);
                oa[i][3] = fmaf(pr[i], vv.w, oa[i][3]);
            }
        }
        float* op = optr[t3];
        #pragma unroll
        for (int i = 0; i < 4; i++) {
            float4 w4 = make_float4(oa[i][0], oa[i][1], oa[i][2], oa[i][3]);
            *(float4*)(op + base + (size_t)(n0 + i) * EDIM + m0) = w4;
        }
    }
}

#define ATTN_SMEM ((4096 + 4160 + 4160) * 4)

// ---------------- host launcher ----------------
extern "C" void kernel_launch(void* const* d_in, const int* in_sizes, int n_in,
                              void* d_out, int out_size)
{
    (void)in_sizes; (void)n_in; (void)out_size;

    const float* x    = (const float*)d_in[0];
    const float* scl  = (const float*)d_in[1];
    const float* sft  = (const float*)d_in[2];
    const float* wq   = (const float*)d_in[3];
    const float* bq   = (const float*)d_in[4];
    const float* wk   = (const float*)d_in[5];
    const float* bk   = (const float*)d_in[6];
    const float* wv   = (const float*)d_in[7];
    const float* bv   = (const float*)d_in[8];
    const float* wvs  = (const float*)d_in[9];
    const float* bvs  = (const float*)d_in[10];
    const float* wvh  = (const float*)d_in[11];
    const float* bvh  = (const float*)d_in[12];
    const float* wpx  = (const float*)d_in[13];
    const float* bpx  = (const float*)d_in[14];
    const float* wps  = (const float*)d_in[15];
    const float* bps  = (const float*)d_in[16];
    const float* wph  = (const float*)d_in[17];
    const float* bph  = (const float*)d_in[18];
    const float* rpb  = (const float*)d_in[19];
    const float* w1x  = (const float*)d_in[20];
    const float* b1x  = (const float*)d_in[21];
    const float* w2x  = (const float*)d_in[22];
    const float* b2x  = (const float*)d_in[23];
    const float* w1s  = (const float*)d_in[24];
    const float* b1s  = (const float*)d_in[25];
    const float* w2s  = (const float*)d_in[26];
    const float* b2s  = (const float*)d_in[27];
    const float* w1h  = (const float*)d_in[28];
    const float* b1h  = (const float*)d_in[29];
    const float* w2h  = (const float*)d_in[30];
    const float* b2h  = (const float*)d_in[31];

    float *p_xw, *p_sw, *p_hw, *p_q, *p_k, *p_v, *p_vs, *p_vh, *p_o, *p_os, *p_oh, *p_hid;
    cudaGetSymbolAddress((void**)&p_xw, g_xw);
    cudaGetSymbolAddress((void**)&p_sw, g_sw);
    cudaGetSymbolAddress((void**)&p_hw, g_hw);
    cudaGetSymbolAddress((void**)&p_q,  g_q);
    cudaGetSymbolAddress((void**)&p_k,  g_k);
    cudaGetSymbolAddress((void**)&p_v,  g_v);
    cudaGetSymbolAddress((void**)&p_vs, g_vs);
    cudaGetSymbolAddress((void**)&p_vh, g_vh);
    cudaGetSymbolAddress((void**)&p_o,  g_o);
    cudaGetSymbolAddress((void**)&p_os, g_os);
    cudaGetSymbolAddress((void**)&p_oh, g_oh);
    cudaGetSymbolAddress((void**)&p_hid, g_hid);

    float* outx = (float*)d_out;
    float* outs = outx + (size_t)TD;
    float* outh = outx + (size_t)2 * TD;

    cudaFuncSetAttribute(attn_kernel, cudaFuncAttributeMaxDynamicSharedMemorySize, ATTN_SMEM);
    cudaFuncSetAttribute(gemm_tf32_v3, cudaFuncAttributeMaxDynamicSharedMemorySize, GEMM_SMEM);

    dim3 blk(256);
    dim3 g512(EDIM / BN, NTOK / BM);    // (2, 512)
    dim3 g2048(EHID / BN, NTOK / BM);   // (8, 512)

    // 1. shift + window partition for x / scale / shift
    gather3<<<NTOK, 128>>>(x, scl, sft, p_xw, p_sw, p_hw);

    // 2. projections (q scaled by HD^-0.5 = 0.125)
    gemm_tf32_v3<<<g512, blk, GEMM_SMEM>>>(p_xw, wq,  bq,  p_q,  nullptr, NTOK, EDIM, EDIM, 0, 0.125f);
    gemm_tf32_v3<<<g512, blk, GEMM_SMEM>>>(p_xw, wk,  bk,  p_k,  nullptr, NTOK, EDIM, EDIM, 0, 1.f);
    gemm_tf32_v3<<<g512, blk, GEMM_SMEM>>>(p_xw, wv,  bv,  p_v,  nullptr, NTOK, EDIM, EDIM, 0, 1.f);
    gemm_tf32_v3<<<g512, blk, GEMM_SMEM>>>(p_sw, wvs, bvs, p_vs, nullptr, NTOK, EDIM, EDIM, 0, 1.f);
    gemm_tf32_v3<<<g512, blk, GEMM_SMEM>>>(p_hw, wvh, bvh, p_vh, nullptr, NTOK, EDIM, EDIM, 0, 1.f);

    // 3. windowed attention (shared softmax, three V streams)
    attn_kernel<<<dim3(1024, 8), 256, ATTN_SMEM>>>(p_q, p_k, p_v, p_vs, p_vh, rpb, p_o, p_os, p_oh);

    // 4. output projections + window reverse + residual (scatter into d_out)
    gemm_tf32_v3<<<g512, blk, GEMM_SMEM>>>(p_o,  wpx, bpx, outx, x,   NTOK, EDIM, EDIM, 3, 1.f);
    gemm_tf32_v3<<<g512, blk, GEMM_SMEM>>>(p_os, wps, bps, outs, scl, NTOK, EDIM, EDIM, 3, 1.f);
    gemm_tf32_v3<<<g512, blk, GEMM_SMEM>>>(p_oh, wph, bph, outh, sft, NTOK, EDIM, EDIM, 3, 1.f);

    // 5. MLPs with residual accumulate
    gemm_tf32_v3<<<g2048, blk, GEMM_SMEM>>>(outx,  w1x, b1x, p_hid, nullptr, NTOK, EHID, EDIM, 1, 1.f);
    gemm_tf32_v3<<<g512,  blk, GEMM_SMEM>>>(p_hid, w2x, b2x, outx,  nullptr, NTOK, EDIM, EHID, 2, 1.f);

    gemm_tf32_v3<<<g2048, blk, GEMM_SMEM>>>(outs,  w1s, b1s, p_hid, nullptr, NTOK, EHID, EDIM, 1, 1.f);
    gemm_tf32_v3<<<g512,  blk, GEMM_SMEM>>>(p_hid, w2s, b2s, outs,  nullptr, NTOK, EDIM, EHID, 2, 1.f);

    gemm_tf32_v3<<<g2048, blk, GEMM_SMEM>>>(outh,  w1h, b1h, p_hid, nullptr, NTOK, EHID, EDIM, 1, 1.f);
    gemm_tf32_v3<<<g512,  blk, GEMM_SMEM>>>(p_hid, w2h, b2h, outh,  nullptr, NTOK, EDIM, EHID, 2, 1.f);
}

// round 12
// speedup vs baseline: 4.2852x; 4.2852x over previous
#include <cuda_runtime.h>
#include <cuda_pipeline.h>
#include <mma.h>

using namespace nvcuda;

#define NTOK 65536          // B * H * W = 16 * 64 * 64
#define EDIM 512
#define EHID 2048
#define TD (NTOK * EDIM)    // elements per (token, dim) tensor

// ---------------- scratch (static device globals; no allocations) ----------------
__device__ float g_xw[TD];
__device__ float g_sw[TD];
__device__ float g_hw[TD];
__device__ float g_q[TD];
__device__ float g_k[TD];
__device__ float g_v[TD];
__device__ float g_vs[TD];
__device__ float g_vh[TD];
__device__ float g_o[TD];
__device__ float g_os[TD];
__device__ float g_oh[TD];
__device__ float g_hid[NTOK * EHID];

// windowed token t -> original token (also the window-reverse scatter target)
__device__ __forceinline__ int winrev_row(int t) {
    int b   = t >> 12;          // 4096 tokens per image
    int win = (t >> 6) & 63;    // wh*8 + ww
    int n   = t & 63;           // nh*8 + nw
    int oh  = (((win >> 3) << 3) + (n >> 3) + 4) & 63;
    int ow  = (((win & 7) << 3) + (n & 7) + 4) & 63;
    return (b << 12) + (oh << 6) + ow;
}

// ---------------- gather: cyclic shift (-4,-4) + window partition ----------------
__global__ __launch_bounds__(128) void gather3(
    const float* __restrict__ x, const float* __restrict__ s, const float* __restrict__ h,
    float* __restrict__ xw, float* __restrict__ sw, float* __restrict__ hw)
{
    int t = blockIdx.x;
    int c = threadIdx.x << 2;
    size_t src = (size_t)winrev_row(t) * EDIM + c;
    size_t dst = (size_t)t * EDIM + c;
    *(float4*)(xw + dst) = *(const float4*)(x + src);
    *(float4*)(sw + dst) = *(const float4*)(s + src);
    *(float4*)(hw + dst) = *(const float4*)(h + src);
}

// ---------------- tf32 wmma GEMM v4: 128x128 tile, padded smem, cp.async ----------
// A: M x K row-major, B: K x N row-major. fp32 operands; HMMA truncates to tf32 (RZ).
// 8 warps, 32x64 warp tile (acc 2x4 = 64 regs) -> regs capped at 128, 2 CTAs/SM.
// mode 0: C = alpha * val
// mode 1: C = relu(val)
// mode 2: C += val                (in-place residual accumulate)
// mode 3: C[map(row)] = res[map(row)] + val   (window-reverse scatter + residual)
#define BM 128
#define BN 128
#define BK 16
#define A_PAD 20                        // 128x16 tile at stride 20 (conflict-free)
#define B_PAD 132                       // 16x128 tile at stride 132
#define A_STAGE (BM * A_PAD)            // 2560 floats
#define B_STAGE (BK * B_PAD)            // 2112 floats
#define GEMM_SMEM ((2 * A_STAGE + 2 * B_STAGE) * 4)   // 37,376 bytes

__global__ __launch_bounds__(256, 2) void gemm_tf32_v4(
    const float* __restrict__ A, const float* __restrict__ Bm,
    const float* __restrict__ bias, float* __restrict__ C,
    const float* __restrict__ res,
    int M, int N, int K, int mode, float alpha)
{
    extern __shared__ float sm[];
    float* As = sm;                     // 2 stages of 128x20
    float* Bs = sm + 2 * A_STAGE;       // 2 stages of 16x132

    int tid = threadIdx.x;
    int warp = tid >> 5;
    int wm = warp >> 1;                 // 0..3: 32-row band
    int wn = warp & 1;                  // 0..1: 64-col band
    int m0 = blockIdx.y * BM;
    int n0 = blockIdx.x * BN;

    wmma::fragment<wmma::accumulator, 16, 16, 8, float> acc[2][4];
    #pragma unroll
    for (int i = 0; i < 2; i++)
        #pragma unroll
        for (int j = 0; j < 4; j++) wmma::fill_fragment(acc[i][j], 0.0f);

    // async tile loader: A 512 float4 (2/thread), B 512 float4 (2/thread)
    auto load_tile = [&](int s, int ko) {
        float* as = As + s * A_STAGE;
        float* bs = Bs + s * B_STAGE;
        #pragma unroll
        for (int i = 0; i < 2; i++) {
            int id = tid * 2 + i;
            int r = id >> 2, c = (id & 3) << 2;
            __pipeline_memcpy_async(as + r * A_PAD + c,
                                    A + (size_t)(m0 + r) * K + ko + c, 16);
        }
        #pragma unroll
        for (int i = 0; i < 2; i++) {
            int id = tid * 2 + i;
            int r = id >> 5, c = (id & 31) << 2;
            __pipeline_memcpy_async(bs + r * B_PAD + c,
                                    Bm + (size_t)(ko + r) * N + n0 + c, 16);
        }
    };

    int ktiles = K / BK;
    load_tile(0, 0);
    __pipeline_commit();

    for (int kt = 0; kt < ktiles; kt++) {
        if (kt + 1 < ktiles) {
            load_tile((kt + 1) & 1, (kt + 1) * BK);
            __pipeline_commit();
        }
        __pipeline_wait_prior(kt + 1 < ktiles ? 1 : 0);
        __syncthreads();

        float* as = As + (kt & 1) * A_STAGE;
        float* bs = Bs + (kt & 1) * B_STAGE;
        #pragma unroll
        for (int ks = 0; ks < BK; ks += 8) {
            wmma::fragment<wmma::matrix_a, 16, 16, 8, wmma::precision::tf32, wmma::row_major> af[2];
            wmma::fragment<wmma::matrix_b, 16, 16, 8, wmma::precision::tf32, wmma::row_major> bf[4];
            #pragma unroll
            for (int i = 0; i < 2; i++)
                wmma::load_matrix_sync(af[i], as + (wm * 32 + i * 16) * A_PAD + ks, A_PAD);
            #pragma unroll
            for (int j = 0; j < 4; j++)
                wmma::load_matrix_sync(bf[j], bs + ks * B_PAD + wn * 64 + j * 16, B_PAD);
            #pragma unroll
            for (int i = 0; i < 2; i++)
                #pragma unroll
                for (int j = 0; j < 4; j++)
                    wmma::mma_sync(acc[i][j], af[i], bf[j], acc[i][j]);
        }
        __syncthreads();
    }

    // epilogue in two 64x128 halves staged at stride 132 (fits in 9344-float smem)
    #pragma unroll 1
    for (int half = 0; half < 2; half++) {
        if ((wm >> 1) == half) {
            int rbase = wm * 32 - half * 64;
            #pragma unroll
            for (int i = 0; i < 2; i++)
                #pragma unroll
                for (int j = 0; j < 4; j++)
                    wmma::store_matrix_sync(sm + (rbase + i * 16) * B_PAD + wn * 64 + j * 16,
                                            acc[i][j], B_PAD, wmma::mem_row_major);
        }
        __syncthreads();
        // 64*128/4 = 2048 float4, 8 per thread
        for (int e = tid; e < 2048; e += 256) {
            int r = e >> 5;
            int c = (e & 31) << 2;
            float4 val = *(float4*)(sm + r * B_PAD + c);
            int gn = n0 + c;
            float4 bb = *(const float4*)(bias + gn);
            val.x += bb.x; val.y += bb.y; val.z += bb.z; val.w += bb.w;
            int gm = m0 + half * 64 + r;
            if (mode == 0) {
                val.x *= alpha; val.y *= alpha; val.z *= alpha; val.w *= alpha;
                *(float4*)(C + (size_t)gm * N + gn) = val;
            } else if (mode == 1) {
                val.x = fmaxf(val.x, 0.f); val.y = fmaxf(val.y, 0.f);
                val.z = fmaxf(val.z, 0.f); val.w = fmaxf(val.w, 0.f);
                *(float4*)(C + (size_t)gm * N + gn) = val;
            } else if (mode == 2) {
                float4 cv = *(float4*)(C + (size_t)gm * N + gn);
                val.x += cv.x; val.y += cv.y; val.z += cv.z; val.w += cv.w;
                *(float4*)(C + (size_t)gm * N + gn) = val;
            } else {
                size_t off = (size_t)winrev_row(gm) * N + gn;
                float4 rv = *(const float4*)(res + off);
                val.x += rv.x; val.y += rv.y; val.z += rv.z; val.w += rv.w;
                *(float4*)(C + off) = val;
            }
        }
        __syncthreads();
    }
}

// ---------------- attention: one block per (window, head) ----------------
// dynamic smem (49,664 B): qs 64x64 (reused for V), ktr stride-65, ps stride-65
#define PS_STRIDE 65
__global__ __launch_bounds__(256) void attn_kernel(
    const float* __restrict__ q, const float* __restrict__ k,
    const float* __restrict__ v, const float* __restrict__ vs, const float* __restrict__ vh,
    const float* __restrict__ rpb,
    float* __restrict__ o, float* __restrict__ os, float* __restrict__ oh)
{
    extern __shared__ float dsm[];
    float* qs  = dsm;                 // 64*64 = 4096
    float* ktr = dsm + 4096;          // 64*65 = 4160, kt[d*65 + m]
    float* ps  = dsm + 4096 + 4160;   // 64*65 = 4160, ps[n*65 + m]

    int win = blockIdx.x;
    int head = blockIdx.y;
    int tid = threadIdx.x;
    size_t base = (size_t)win * 64 * EDIM + head * 64;

    for (int f4 = tid; f4 < 1024; f4 += 256) {
        int n = f4 >> 4;
        int c = (f4 & 15) << 2;
        float4 qv = *(const float4*)(q + base + (size_t)n * EDIM + c);
        *(float4*)(qs + n * 64 + c) = qv;
        float4 kv = *(const float4*)(k + base + (size_t)n * EDIM + c);
        ktr[(c + 0) * 65 + n] = kv.x;
        ktr[(c + 1) * 65 + n] = kv.y;
        ktr[(c + 2) * 65 + n] = kv.z;
        ktr[(c + 3) * 65 + n] = kv.w;
    }
    __syncthreads();

    int n0 = (tid >> 4) << 2;
    int m0 = (tid & 15) << 2;

    float acc[4][4];
    #pragma unroll
    for (int i = 0; i < 4; i++)
        #pragma unroll
        for (int j = 0; j < 4; j++) acc[i][j] = 0.f;

    #pragma unroll 4
    for (int d = 0; d < 64; d++) {
        float qr[4], kr[4];
        #pragma unroll
        for (int i = 0; i < 4; i++) qr[i] = qs[(n0 + i) * 64 + d];
        #pragma unroll
        for (int j = 0; j < 4; j++) kr[j] = ktr[d * 65 + m0 + j];
        #pragma unroll
        for (int i = 0; i < 4; i++)
            #pragma unroll
            for (int j = 0; j < 4; j++)
                acc[i][j] = fmaf(qr[i], kr[j], acc[i][j]);
    }

    // rel-pos bias + shifted-window mask (window coordinates, unrolled mask grid)
    int wi = win & 63;
    int wh = wi >> 3, ww = wi & 7;
    #pragma unroll
    for (int i = 0; i < 4; i++) {
        int nn = n0 + i;
        int ni = nn >> 3, nj = nn & 7;
        int yn = wh * 8 + ni, xn = ww * 8 + nj;
        int idn = ((yn < 56) ? 0 : (yn < 60) ? 1 : 2) * 3 +
                  ((xn < 56) ? 0 : (xn < 60) ? 1 : 2);
        #pragma unroll
        for (int j = 0; j < 4; j++) {
            int mm = m0 + j;
            int mi = mm >> 3, mj = mm & 7;
            float rb = rpb[(((ni - mi + 7) * 15) + (nj - mj + 7)) * 8 + head];
            int ym = wh * 8 + mi, xm = ww * 8 + mj;
            int idm = ((ym < 56) ? 0 : (ym < 60) ? 1 : 2) * 3 +
                      ((xm < 56) ? 0 : (xm < 60) ? 1 : 2);
            float msk = (idn == idm) ? 0.f : -100.f;
            ps[nn * PS_STRIDE + mm] = acc[i][j] + rb + msk;
        }
    }
    __syncthreads();

    // softmax: one thread per row (stride-65 -> conflict-free)
    if (tid < 64) {
        float mx = -1e30f;
        for (int m = 0; m < 64; m++) mx = fmaxf(mx, ps[tid * PS_STRIDE + m]);
        float sum = 0.f;
        for (int m = 0; m < 64; m++) {
            float e = __expf(ps[tid * PS_STRIDE + m] - mx);
            ps[tid * PS_STRIDE + m] = e;
            sum += e;
        }
        float inv = 1.f / sum;
        for (int m = 0; m < 64; m++) ps[tid * PS_STRIDE + m] *= inv;
    }

    const float* vptr[3] = {v, vs, vh};
    float* optr[3] = {o, os, oh};
    #pragma unroll 1
    for (int t3 = 0; t3 < 3; t3++) {
        __syncthreads();                                  // qs free to reuse
        const float* vp = vptr[t3];
        for (int f4 = tid; f4 < 1024; f4 += 256) {
            int n = f4 >> 4;
            int c = (f4 & 15) << 2;
            *(float4*)(qs + n * 64 + c) = *(const float4*)(vp + base + (size_t)n * EDIM + c);
        }
        __syncthreads();
        float oa[4][4];
        #pragma unroll
        for (int i = 0; i < 4; i++)
            #pragma unroll
            for (int j = 0; j < 4; j++) oa[i][j] = 0.f;
        #pragma unroll 4
        for (int m = 0; m < 64; m++) {
            float pr[4];
            #pragma unroll
            for (int i = 0; i < 4; i++) pr[i] = ps[(n0 + i) * PS_STRIDE + m];
            float4 vv = *(const float4*)(qs + m * 64 + m0);
            #pragma unroll
            for (int i = 0; i < 4; i++) {
                oa[i][0] = fmaf(pr[i], vv.x, oa[i][0]);
                oa[i][1] = fmaf(pr[i], vv.y, oa[i][1]);
                oa[i][2] = fmaf(pr[i], vv.z, oa[i][2]);
                oa[i][3] = fmaf(pr[i], vv.w, oa[i][3]);
            }
        }
        float* op = optr[t3];
        #pragma unroll
        for (int i = 0; i < 4; i++) {
            float4 w4 = make_float4(oa[i][0], oa[i][1], oa[i][2], oa[i][3]);
            *(float4*)(op + base + (size_t)(n0 + i) * EDIM + m0) = w4;
        }
    }
}

#define ATTN_SMEM ((4096 + 4160 + 4160) * 4)

// ---------------- host launcher ----------------
extern "C" void kernel_launch(void* const* d_in, const int* in_sizes, int n_in,
                              void* d_out, int out_size)
{
    (void)in_sizes; (void)n_in; (void)out_size;

    const float* x    = (const float*)d_in[0];
    const float* scl  = (const float*)d_in[1];
    const float* sft  = (const float*)d_in[2];
    const float* wq   = (const float*)d_in[3];
    const float* bq   = (const float*)d_in[4];
    const float* wk   = (const float*)d_in[5];
    const float* bk   = (const float*)d_in[6];
    const float* wv   = (const float*)d_in[7];
    const float* bv   = (const float*)d_in[8];
    const float* wvs  = (const float*)d_in[9];
    const float* bvs  = (const float*)d_in[10];
    const float* wvh  = (const float*)d_in[11];
    const float* bvh  = (const float*)d_in[12];
    const float* wpx  = (const float*)d_in[13];
    const float* bpx  = (const float*)d_in[14];
    const float* wps  = (const float*)d_in[15];
    const float* bps  = (const float*)d_in[16];
    const float* wph  = (const float*)d_in[17];
    const float* bph  = (const float*)d_in[18];
    const float* rpb  = (const float*)d_in[19];
    const float* w1x  = (const float*)d_in[20];
    const float* b1x  = (const float*)d_in[21];
    const float* w2x  = (const float*)d_in[22];
    const float* b2x  = (const float*)d_in[23];
    const float* w1s  = (const float*)d_in[24];
    const float* b1s  = (const float*)d_in[25];
    const float* w2s  = (const float*)d_in[26];
    const float* b2s  = (const float*)d_in[27];
    const float* w1h  = (const float*)d_in[28];
    const float* b1h  = (const float*)d_in[29];
    const float* w2h  = (const float*)d_in[30];
    const float* b2h  = (const float*)d_in[31];

    float *p_xw, *p_sw, *p_hw, *p_q, *p_k, *p_v, *p_vs, *p_vh, *p_o, *p_os, *p_oh, *p_hid;
    cudaGetSymbolAddress((void**)&p_xw, g_xw);
    cudaGetSymbolAddress((void**)&p_sw, g_sw);
    cudaGetSymbolAddress((void**)&p_hw, g_hw);
    cudaGetSymbolAddress((void**)&p_q,  g_q);
    cudaGetSymbolAddress((void**)&p_k,  g_k);
    cudaGetSymbolAddress((void**)&p_v,  g_v);
    cudaGetSymbolAddress((void**)&p_vs, g_vs);
    cudaGetSymbolAddress((void**)&p_vh, g_vh);
    cudaGetSymbolAddress((void**)&p_o,  g_o);
    cudaGetSymbolAddress((void**)&p_os, g_os);
    cudaGetSymbolAddress((void**)&p_oh, g_oh);
    cudaGetSymbolAddress((void**)&p_hid, g_hid);

    float* outx = (float*)d_out;
    float* outs = outx + (size_t)TD;
    float* outh = outx + (size_t)2 * TD;

    cudaFuncSetAttribute(attn_kernel, cudaFuncAttributeMaxDynamicSharedMemorySize, ATTN_SMEM);
    cudaFuncSetAttribute(gemm_tf32_v4, cudaFuncAttributeMaxDynamicSharedMemorySize, GEMM_SMEM);

    dim3 blk(256);
    dim3 g512(EDIM / BN, NTOK / BM);    // (4, 512)
    dim3 g2048(EHID / BN, NTOK / BM);   // (16, 512)

    // 1. shift + window partition for x / scale / shift
    gather3<<<NTOK, 128>>>(x, scl, sft, p_xw, p_sw, p_hw);

    // 2. projections (q scaled by HD^-0.5 = 0.125)
    gemm_tf32_v4<<<g512, blk, GEMM_SMEM>>>(p_xw, wq,  bq,  p_q,  nullptr, NTOK, EDIM, EDIM, 0, 0.125f);
    gemm_tf32_v4<<<g512, blk, GEMM_SMEM>>>(p_xw, wk,  bk,  p_k,  nullptr, NTOK, EDIM, EDIM, 0, 1.f);
    gemm_tf32_v4<<<g512, blk, GEMM_SMEM>>>(p_xw, wv,  bv,  p_v,  nullptr, NTOK, EDIM, EDIM, 0, 1.f);
    gemm_tf32_v4<<<g512, blk, GEMM_SMEM>>>(p_sw, wvs, bvs, p_vs, nullptr, NTOK, EDIM, EDIM, 0, 1.f);
    gemm_tf32_v4<<<g512, blk, GEMM_SMEM>>>(p_hw, wvh, bvh, p_vh, nullptr, NTOK, EDIM, EDIM, 0, 1.f);

    // 3. windowed attention (shared softmax, three V streams)
    attn_kernel<<<dim3(1024, 8), 256, ATTN_SMEM>>>(p_q, p_k, p_v, p_vs, p_vh, rpb, p_o, p_os, p_oh);

    // 4. output projections + window reverse + residual (scatter into d_out)
    gemm_tf32_v4<<<g512, blk, GEMM_SMEM>>>(p_o,  wpx, bpx, outx, x,   NTOK, EDIM, EDIM, 3, 1.f);
    gemm_tf32_v4<<<g512, blk, GEMM_SMEM>>>(p_os, wps, bps, outs, scl, NTOK, EDIM, EDIM, 3, 1.f);
    gemm_tf32_v4<<<g512, blk, GEMM_SMEM>>>(p_oh, wph, bph, outh, sft, NTOK, EDIM, EDIM, 3, 1.f);

    // 5. MLPs with residual accumulate
    gemm_tf32_v4<<<g2048, blk, GEMM_SMEM>>>(outx,  w1x, b1x, p_hid, nullptr, NTOK, EHID, EDIM, 1, 1.f);
    gemm_tf32_v4<<<g512,  blk, GEMM_SMEM>>>(p_hid, w2x, b2x, outx,  nullptr, NTOK, EDIM, EHID, 2, 1.f);

    gemm_tf32_v4<<<g2048, blk, GEMM_SMEM>>>(outs,  w1s, b1s, p_hid, nullptr, NTOK, EHID, EDIM, 1, 1.f);
    gemm_tf32_v4<<<g512,  blk, GEMM_SMEM>>>(p_hid, w2s, b2s, outs,  nullptr, NTOK, EDIM, EHID, 2, 1.f);

    gemm_tf32_v4<<<g2048, blk, GEMM_SMEM>>>(outh,  w1h, b1h, p_hid, nullptr, NTOK, EHID, EDIM, 1, 1.f);
    gemm_tf32_v4<<<g512,  blk, GEMM_SMEM>>>(p_hid, w2h, b2h, outh,  nullptr, NTOK, EDIM, EHID, 2, 1.f);
}